// round 7
// baseline (speedup 1.0000x reference)
#include <cuda_runtime.h>

// ---------------------------------------------------------------------------
// GraphProbeFeatures: fused per-batch SIREN + probe projections + LayerNorm.
// R5: revert to 512-thread / 8x4-tile structure (R3) which balances smem
// crossbar vs fma issue; keep __sinf; Phase B loads h1 as float4 broadcasts
// (crossbar 8->5 cyc/k/warp); tail phases (E / z3 / z0) spread across
// disjoint warp groups to cut barrier imbalance.
// ---------------------------------------------------------------------------

namespace gpf {
constexpr int Bn   = 128;
constexpr int Nn   = 4096;
constexpr int Hh   = 128;
constexpr int Pp   = 128;
constexpr int DOUT = 3;
constexpr int ROWS = 2 + Hh + Hh + DOUT;   // 261 output rows per batch
constexpr int TILE = 64;
constexpr int NTILES = Nn / TILE;          // 64
constexpr int NTHREADS = 512;
constexpr int HS   = 136;                  // padded row stride for h tiles
constexpr float W0F = 30.0f;
constexpr float EPS = 1e-5f;

// shared-memory layout (float offsets)
constexpr int OFF_W1  = 0;                       // 128x128 w1 (stride 128)
constexpr int OFF_H1  = OFF_W1  + Hh * Hh;       // 64x136
constexpr int OFF_H2  = OFF_H1  + TILE * HS;     // 64x136
constexpr int OFF_PW1 = OFF_H2  + TILE * HS;     // 64x128  (also zs epilogue, with OFF_PW2)
constexpr int OFF_PW2 = OFF_PW1 + TILE * Pp;     // 64x128
constexpr int OFF_W0  = OFF_PW2 + TILE * Pp;     // 2x128
constexpr int OFF_B0  = OFF_W0  + 2 * Hh;        // 128
constexpr int OFF_B1  = OFF_B0  + Hh;            // 128
constexpr int OFF_W2  = OFF_B1  + Hh;            // 128x4 (stride 4, col 3 unused)
constexpr int OFF_B2  = OFF_W2  + Hh * 4;        // 4
constexpr int OFF_H3  = OFF_B2  + 4;             // 64x4
constexpr int OFF_Z5  = OFF_H3  + TILE * 4;      // 5x128 (z0 rows + z3 rows)
constexpr int SMEM_FLOATS = OFF_Z5 + 5 * Pp;     // 52100 floats
constexpr int SMEM_BYTES  = SMEM_FLOATS * 4;     // 208400 B
}  // namespace gpf

// ---- packed f32x2 helpers --------------------------------------------------
__device__ __forceinline__ unsigned long long pk2(float x, float y) {
    unsigned long long r;
    asm("mov.b64 %0, {%1, %2};" : "=l"(r) : "f"(x), "f"(y));
    return r;
}
__device__ __forceinline__ float2 upk2(unsigned long long v) {
    float2 f;
    asm("mov.b64 {%0, %1}, %2;" : "=f"(f.x), "=f"(f.y) : "l"(v));
    return f;
}
__device__ __forceinline__ void fma2(unsigned long long& acc,
                                     unsigned long long a, unsigned long long b) {
    asm("fma.rn.f32x2 %0, %1, %2, %0;" : "+l"(acc) : "l"(a), "l"(b));
}

// ---- warp LayerNorm over one row of 128 (lane holds 4 contiguous values) ---
__device__ __forceinline__ void ln_row_write(float4 v, const float* __restrict__ g,
                                             const float* __restrict__ bb,
                                             float* __restrict__ orow, int lane) {
    float s = (v.x + v.y) + (v.z + v.w);
    #pragma unroll
    for (int o = 16; o > 0; o >>= 1) s += __shfl_xor_sync(0xffffffffu, s, o);
    float m = s * (1.0f / 128.0f);
    float cx = v.x - m, cy = v.y - m, cz = v.z - m, cw = v.w - m;
    float q = (cx * cx + cy * cy) + (cz * cz + cw * cw);
    #pragma unroll
    for (int o = 16; o > 0; o >>= 1) q += __shfl_xor_sync(0xffffffffu, q, o);
    float inv = rsqrtf(q * (1.0f / 128.0f) + gpf::EPS);
    float4 gv = *(const float4*)(g + lane * 4);
    float4 bv = *(const float4*)(bb + lane * 4);
    float4 ov;
    ov.x = cx * inv * gv.x + bv.x;
    ov.y = cy * inv * gv.y + bv.y;
    ov.z = cz * inv * gv.z + bv.z;
    ov.w = cw * inv * gv.w + bv.w;
    *(float4*)(orow + lane * 4) = ov;
}

__global__ __launch_bounds__(gpf::NTHREADS, 1)
void gpf_kernel(const float* __restrict__ w0g, const float* __restrict__ w1g,
                const float* __restrict__ w2g, const float* __restrict__ b0g,
                const float* __restrict__ b1g, const float* __restrict__ b2g,
                const float* __restrict__ xg,  const float* __restrict__ pwg,
                const float* __restrict__ pbg, const float* __restrict__ lngg,
                const float* __restrict__ lnbg, float* __restrict__ outg) {
    using namespace gpf;
    extern __shared__ float sm[];
    const int b    = blockIdx.x;
    const int t    = threadIdx.x;
    const int lane = t & 31;
    const int wid  = t >> 5;   // 0..15

    float* w1s  = sm + OFF_W1;
    float* h1s  = sm + OFF_H1;
    float* h2s  = sm + OFF_H2;
    float* pw1s = sm + OFF_PW1;
    float* pw2s = sm + OFF_PW2;
    float* zs   = sm + OFF_PW1;  // epilogue reuse: 128x128
    float* w0s  = sm + OFF_W0;
    float* b0s  = sm + OFF_B0;
    float* b1s  = sm + OFF_B1;
    float* w2s  = sm + OFF_W2;
    float* b2s  = sm + OFF_B2;
    float* h3s  = sm + OFF_H3;
    float* z5s  = sm + OFF_Z5;

    // ---- one-time loads: w1 (64KB), w0/b0/b1/w2/b2 ----
    {
        const float4* src = (const float4*)(w1g + (size_t)b * Hh * Hh);
        float4* dst = (float4*)w1s;
        #pragma unroll
        for (int i = 0; i < 8; ++i) dst[t + i * NTHREADS] = src[t + i * NTHREADS];
        if (t < 256)      w0s[t]       = w0g[b * 256 + t];
        else if (t < 384) b0s[t - 256] = b0g[b * 128 + (t - 256)];
        else              b1s[t - 384] = b1g[b * 128 + (t - 384)];
        if (t < 128) {
            w2s[t * 4 + 0] = w2g[b * 384 + t * 3 + 0];
            w2s[t * 4 + 1] = w2g[b * 384 + t * 3 + 1];
            w2s[t * 4 + 2] = w2g[b * 384 + t * 3 + 2];
        }
        if (t < 3) b2s[t] = b2g[b * 3 + t];
    }

    // ---- persistent accumulators ----
    // az*[di][j] = packed pair ( z[d0+2*di][p0+j], z[d0+2*di+1][p0+j] )
    unsigned long long az1[4][4], az2[4][4];
    #pragma unroll
    for (int i = 0; i < 4; ++i)
        #pragma unroll
        for (int j = 0; j < 4; ++j) { az1[i][j] = 0ull; az2[i][j] = 0ull; }
    float z3acc  = 0.0f;  // valid for t < 384:   z3[j][p], j=t>>7, p=t&127
    float z0acc0 = 0.0f;  // valid for t >= 384:  z0[0][p], p=t-384
    float z0acc1 = 0.0f;  // valid for t >= 384:  z0[1][p], p=t-384

    const int d0 = wid * 8;    // z-GEMM: 8 d-rows per thread
    const int p0 = lane * 4;   //         4 p-cols per thread

    for (int tile = 0; tile < NTILES; ++tile) {
        const int n0 = tile * TILE;
        __syncthreads();  // previous tile's consumers done before overwriting tiles

        // ---- Phase A: h1 tile (layer 1 + sin) and pw1/pw2 tiles ----
        #pragma unroll
        for (int it = 0; it < 16; ++it) {
            int idx = t + it * NTHREADS;          // 0..8191
            int n = idx >> 7, h = idx & 127;
            float x0 = xg[(n0 + n) * 2 + 0];
            float x1 = xg[(n0 + n) * 2 + 1];
            float a = fmaf(x0, w0s[h], fmaf(x1, w0s[128 + h], b0s[h]));
            h1s[n * HS + h] = __sinf(W0F * a);
        }
        {
            const float4* s1 = (const float4*)(pwg + (size_t)1 * Nn * Pp + (size_t)n0 * Pp);
            const float4* s2 = (const float4*)(pwg + (size_t)2 * Nn * Pp + (size_t)n0 * Pp);
            float4* dt1 = (float4*)pw1s;
            float4* dt2 = (float4*)pw2s;
            #pragma unroll
            for (int it = 0; it < 4; ++it) {
                dt1[t + it * NTHREADS] = s1[t + it * NTHREADS];
                dt2[t + it * NTHREADS] = s2[t + it * NTHREADS];
            }
        }
        __syncthreads();

        // ---- Phase B: h2 = sin(30*(h1 @ w1 + b1)), 4n x 4o per thread.
        //      k in blocks of 4: h1 rows fetched as float4 broadcasts (1 LDS
        //      instead of 4 scalars) -> Phase B crossbar 8->5 cyc/k/warp. ----
        {
            const int nb = wid * 4;
            const int ob = lane * 4;
            unsigned long long acc[4][2];
            #pragma unroll
            for (int i = 0; i < 4; ++i) { acc[i][0] = 0ull; acc[i][1] = 0ull; }
            #pragma unroll 2
            for (int k4 = 0; k4 < Hh; k4 += 4) {
                float a0[4], a1[4], a2[4], a3[4];
                *(float4*)a0 = *(const float4*)(h1s + (nb + 0) * HS + k4);
                *(float4*)a1 = *(const float4*)(h1s + (nb + 1) * HS + k4);
                *(float4*)a2 = *(const float4*)(h1s + (nb + 2) * HS + k4);
                *(float4*)a3 = *(const float4*)(h1s + (nb + 3) * HS + k4);
                #pragma unroll
                for (int kk = 0; kk < 4; ++kk) {
                    ulonglong2 bp = *(const ulonglong2*)(w1s + (k4 + kk) * Hh + ob);
                    unsigned long long ad;
                    ad = pk2(a0[kk], a0[kk]); fma2(acc[0][0], ad, bp.x); fma2(acc[0][1], ad, bp.y);
                    ad = pk2(a1[kk], a1[kk]); fma2(acc[1][0], ad, bp.x); fma2(acc[1][1], ad, bp.y);
                    ad = pk2(a2[kk], a2[kk]); fma2(acc[2][0], ad, bp.x); fma2(acc[2][1], ad, bp.y);
                    ad = pk2(a3[kk], a3[kk]); fma2(acc[3][0], ad, bp.x); fma2(acc[3][1], ad, bp.y);
                }
            }
            float bb0 = b1s[ob], bb1 = b1s[ob + 1], bb2 = b1s[ob + 2], bb3 = b1s[ob + 3];
            #pragma unroll
            for (int i = 0; i < 4; ++i) {
                float2 u = upk2(acc[i][0]);
                float2 v = upk2(acc[i][1]);
                float4 o;
                o.x = __sinf(W0F * (u.x + bb0));
                o.y = __sinf(W0F * (u.y + bb1));
                o.z = __sinf(W0F * (v.x + bb2));
                o.w = __sinf(W0F * (v.y + bb3));
                *(float4*)(h2s + (nb + i) * HS + ob) = o;
            }
        }

        // ---- Phase C: z1 += h1^T @ pw1 (reads only h1s; hoisted above the
        //      h2-consumer barrier so the barrier hides behind this FMA stream) ----
        #pragma unroll 2
        for (int n = 0; n < TILE; ++n) {
            ulonglong2 A0 = *(const ulonglong2*)(h1s + n * HS + d0);
            ulonglong2 A1 = *(const ulonglong2*)(h1s + n * HS + d0 + 4);
            float4 bv = *(const float4*)(pw1s + n * Pp + p0);
            unsigned long long bd0 = pk2(bv.x, bv.x), bd1 = pk2(bv.y, bv.y);
            unsigned long long bd2 = pk2(bv.z, bv.z), bd3 = pk2(bv.w, bv.w);
            fma2(az1[0][0], A0.x, bd0); fma2(az1[0][1], A0.x, bd1);
            fma2(az1[0][2], A0.x, bd2); fma2(az1[0][3], A0.x, bd3);
            fma2(az1[1][0], A0.y, bd0); fma2(az1[1][1], A0.y, bd1);
            fma2(az1[1][2], A0.y, bd2); fma2(az1[1][3], A0.y, bd3);
            fma2(az1[2][0], A1.x, bd0); fma2(az1[2][1], A1.x, bd1);
            fma2(az1[2][2], A1.x, bd2); fma2(az1[2][3], A1.x, bd3);
            fma2(az1[3][0], A1.y, bd0); fma2(az1[3][1], A1.y, bd1);
            fma2(az1[3][2], A1.y, bd2); fma2(az1[3][3], A1.y, bd3);
        }

        // h2s fully written (Phase B) before ANY thread reads other warps' rows
        __syncthreads();

        // ---- Phase E (warps 10-15): h3[n][j] = h2[n,:] . w2[:,j] + b2[j] ----
        if (t >= 320) {
            int u = t - 320;               // 0..191
            int n = u / 3;
            int j = u - n * 3;
            float acc = b2s[j];
            #pragma unroll 8
            for (int k = 0; k < Hh; ++k)
                acc = fmaf(h2s[n * HS + k], w2s[k * 4 + j], acc);
            h3s[n * 4 + j] = acc;
        }

        // ---- Phase D: z2 += h2^T @ pw2 ----
        #pragma unroll 2
        for (int n = 0; n < TILE; ++n) {
            ulonglong2 A0 = *(const ulonglong2*)(h2s + n * HS + d0);
            ulonglong2 A1 = *(const ulonglong2*)(h2s + n * HS + d0 + 4);
            float4 bv = *(const float4*)(pw2s + n * Pp + p0);
            unsigned long long bd0 = pk2(bv.x, bv.x), bd1 = pk2(bv.y, bv.y);
            unsigned long long bd2 = pk2(bv.z, bv.z), bd3 = pk2(bv.w, bv.w);
            fma2(az2[0][0], A0.x, bd0); fma2(az2[0][1], A0.x, bd1);
            fma2(az2[0][2], A0.x, bd2); fma2(az2[0][3], A0.x, bd3);
            fma2(az2[1][0], A0.y, bd0); fma2(az2[1][1], A0.y, bd1);
            fma2(az2[1][2], A0.y, bd2); fma2(az2[1][3], A0.y, bd3);
            fma2(az2[2][0], A1.x, bd0); fma2(az2[2][1], A1.x, bd1);
            fma2(az2[2][2], A1.x, bd2); fma2(az2[2][3], A1.x, bd3);
            fma2(az2[3][0], A1.y, bd0); fma2(az2[3][1], A1.y, bd1);
            fma2(az2[3][2], A1.y, bd2); fma2(az2[3][3], A1.y, bd3);
        }
        __syncthreads();

        // ---- Phase F: z3 += h3^T @ pw3 on warps 0-11 (pw3 streamed from L2) ----
        if (t < 384) {
            int j = t >> 7, p = t & 127;
            const float* pw3 = pwg + (size_t)3 * Nn * Pp + (size_t)n0 * Pp + p;
            float ta = 0.0f, tb = 0.0f;
            #pragma unroll 8
            for (int n = 0; n < TILE; n += 2) {
                ta = fmaf(h3s[n * 4 + j],       pw3[n * Pp],       ta);
                tb = fmaf(h3s[(n + 1) * 4 + j], pw3[(n + 1) * Pp], tb);
            }
            z3acc += ta + tb;
        } else {
            // ---- z0 partial on warps 12-15: z0[0..1][p] += x^T @ pw0 ----
            int p = t - 384;
            const float* pw0 = pwg + (size_t)n0 * Pp + p;
            const float* xp  = xg + n0 * 2;
            float a0 = 0.0f, a1 = 0.0f;
            #pragma unroll 8
            for (int n = 0; n < TILE; ++n) {
                float w = pw0[n * Pp];
                a0 = fmaf(xp[n * 2],     w, a0);
                a1 = fmaf(xp[n * 2 + 1], w, a1);
            }
            z0acc0 += a0;
            z0acc1 += a1;
        }
    }

    // =========================== epilogue ===========================
    __syncthreads();

    // ---- feat1 (h1 projection): rows 2..129 ----
    {
        const float* pb1 = pbg + 128;
        float q0 = pb1[p0], q1 = pb1[p0 + 1], q2 = pb1[p0 + 2], q3 = pb1[p0 + 3];
        #pragma unroll
        for (int di = 0; di < 4; ++di) {
            float2 a0 = upk2(az1[di][0]);
            float2 a1 = upk2(az1[di][1]);
            float2 a2 = upk2(az1[di][2]);
            float2 a3 = upk2(az1[di][3]);
            float4 r0 = {a0.x + q0, a1.x + q1, a2.x + q2, a3.x + q3};
            float4 r1 = {a0.y + q0, a1.y + q1, a2.y + q2, a3.y + q3};
            *(float4*)(zs + (d0 + 2 * di) * Pp + p0)     = r0;
            *(float4*)(zs + (d0 + 2 * di + 1) * Pp + p0) = r1;
        }
    }
    __syncthreads();
    {
        const float* g  = lngg + 128;
        const float* bb = lnbg + 128;
        #pragma unroll
        for (int r = 0; r < 8; ++r) {
            int row = wid * 8 + r;
            float4 v = *(const float4*)(zs + row * Pp + lane * 4);
            ln_row_write(v, g, bb, outg + ((size_t)b * ROWS + 2 + row) * Pp, lane);
        }
    }
    __syncthreads();

    // ---- feat2 (h2 projection): rows 130..257 ----
    {
        const float* pb2 = pbg + 256;
        float q0 = pb2[p0], q1 = pb2[p0 + 1], q2 = pb2[p0 + 2], q3 = pb2[p0 + 3];
        #pragma unroll
        for (int di = 0; di < 4; ++di) {
            float2 a0 = upk2(az2[di][0]);
            float2 a1 = upk2(az2[di][1]);
            float2 a2 = upk2(az2[di][2]);
            float2 a3 = upk2(az2[di][3]);
            float4 r0 = {a0.x + q0, a1.x + q1, a2.x + q2, a3.x + q3};
            float4 r1 = {a0.y + q0, a1.y + q1, a2.y + q2, a3.y + q3};
            *(float4*)(zs + (d0 + 2 * di) * Pp + p0)     = r0;
            *(float4*)(zs + (d0 + 2 * di + 1) * Pp + p0) = r1;
        }
    }
    __syncthreads();
    {
        const float* g  = lngg + 256;
        const float* bb = lnbg + 256;
        #pragma unroll
        for (int r = 0; r < 8; ++r) {
            int row = wid * 8 + r;
            float4 v = *(const float4*)(zs + row * Pp + lane * 4);
            ln_row_write(v, g, bb, outg + ((size_t)b * ROWS + 130 + row) * Pp, lane);
        }
    }

    // ---- feat0 (x projection, rows 0..1) and feat3 (h3 projection, rows 258..260) ----
    if (t >= 384) {
        int p = t - 384;
        z5s[p]      = z0acc0 + pbg[p];
        z5s[Pp + p] = z0acc1 + pbg[p];
    }
    if (t < 384) {
        int j = t >> 7, p = t & 127;
        z5s[(2 + j) * Pp + p] = z3acc + pbg[3 * 128 + p];
    }
    __syncthreads();
    if (wid < 5) {
        int row    = wid;                       // 0,1 -> z0 ; 2,3,4 -> z3
        int feat   = (row < 2) ? 0 : 3;
        int outrow = (row < 2) ? row : (256 + row);  // 258,259,260
        float4 v = *(const float4*)(z5s + row * Pp + lane * 4);
        ln_row_write(v, lngg + feat * 128, lnbg + feat * 128,
                     outg + ((size_t)b * ROWS + outrow) * Pp, lane);
    }
}

extern "C" void kernel_launch(void* const* d_in, const int* in_sizes, int n_in,
                              void* d_out, int out_size) {
    (void)in_sizes; (void)n_in; (void)out_size;
    const float* w0g  = (const float*)d_in[0];
    const float* w1g  = (const float*)d_in[1];
    const float* w2g  = (const float*)d_in[2];
    const float* b0g  = (const float*)d_in[3];
    const float* b1g  = (const float*)d_in[4];
    const float* b2g  = (const float*)d_in[5];
    const float* xg   = (const float*)d_in[6];
    const float* pwg  = (const float*)d_in[7];
    const float* pbg  = (const float*)d_in[8];
    const float* lngg = (const float*)d_in[9];
    const float* lnbg = (const float*)d_in[10];
    float* outg = (float*)d_out;

    cudaFuncSetAttribute(gpf_kernel, cudaFuncAttributeMaxDynamicSharedMemorySize,
                         gpf::SMEM_BYTES);
    gpf_kernel<<<gpf::Bn, gpf::NTHREADS, gpf::SMEM_BYTES>>>(
        w0g, w1g, w2g, b0g, b1g, b2g, xg, pwg, pbg, lngg, lnbg, outg);
}

// round 9
// speedup vs baseline: 1.1393x; 1.1393x over previous
#include <cuda_runtime.h>
#include <cuda_bf16.h>
#include <cstdint>

namespace gpf {
constexpr int Bn=128, Nn=4096, Pp=128, Hh=128, ROWS=261, TILE=64, NTILES=64, NT=512;
constexpr float W0F=30.f, EPS=1e-5f;
constexpr int HB=272;                 // bf16 tile row stride (bytes), conflict-free for LDSM
constexpr int TB=TILE*HB;             // 17408
constexpr int BY_W1=0;                // 128x128 f32 w1 (64KB); epilogue reuses as zs
constexpr int BY_H1H=65536, BY_H1L=BY_H1H+TB, BY_H2H=BY_H1L+TB, BY_H2L=BY_H2H+TB;
constexpr int BY_Q1H=BY_H2L+TB, BY_Q1L=BY_Q1H+TB, BY_Q2H=BY_Q1L+TB, BY_Q2L=BY_Q2H+TB;
constexpr int BY_W0=BY_Q2L+TB;        // 204800
constexpr int BY_B0=BY_W0+1024, BY_B1=BY_B0+512, BY_W2=BY_B1+512, BY_B2=BY_W2+2048;
constexpr int BY_H3=BY_B2+32, BY_Z5=BY_H3+1024;
constexpr int SMEM_BYTES=BY_Z5+2560;  // 212512
}

#define LDSM4T(d,a) asm volatile( \
  "ldmatrix.sync.aligned.m8n8.x4.trans.shared.b16 {%0,%1,%2,%3},[%4];" \
  :"=r"((d)[0]),"=r"((d)[1]),"=r"((d)[2]),"=r"((d)[3]):"r"(a))
#define MMAB(c,a,b0,b1) asm volatile( \
  "mma.sync.aligned.m16n8k16.row.col.f32.bf16.bf16.f32 " \
  "{%0,%1,%2,%3},{%4,%5,%6,%7},{%8,%9},{%0,%1,%2,%3};" \
  :"+f"((c)[0]),"+f"((c)[1]),"+f"((c)[2]),"+f"((c)[3]) \
  :"r"((a)[0]),"r"((a)[1]),"r"((a)[2]),"r"((a)[3]),"r"(b0),"r"(b1))

__device__ __forceinline__ uint32_t smem_u32(const void* p){
  uint32_t a; asm("{ .reg .u64 t; cvta.to.shared.u64 t, %1; cvt.u32.u64 %0, t; }":"=r"(a):"l"(p)); return a;
}
__device__ __forceinline__ uint32_t bfpair(float a, float b, uint32_t& lo){
  __nv_bfloat16 ha=__float2bfloat16(a), hb=__float2bfloat16(b);
  __nv_bfloat162 l; l.x=__float2bfloat16(a-__bfloat162float(ha)); l.y=__float2bfloat16(b-__bfloat162float(hb));
  lo=*(uint32_t*)&l;
  __nv_bfloat162 h; h.x=ha; h.y=hb; return *(uint32_t*)&h;
}
__device__ __forceinline__ float2 b2f(uint32_t u){ return __bfloat1622float2(*(__nv_bfloat162*)&u); }
__device__ __forceinline__ unsigned long long pk2(float x, float y){
  unsigned long long r; asm("mov.b64 %0, {%1, %2};":"=l"(r):"f"(x),"f"(y)); return r;
}
__device__ __forceinline__ float2 upk2(unsigned long long v){
  float2 f; asm("mov.b64 {%0, %1}, %2;":"=f"(f.x),"=f"(f.y):"l"(v)); return f;
}
__device__ __forceinline__ void fma2(unsigned long long& a, unsigned long long x, unsigned long long y){
  asm("fma.rn.f32x2 %0, %1, %2, %0;":"+l"(a):"l"(x),"l"(y));
}
__device__ __forceinline__ void ln_row_write(float4 v, const float* g, const float* bb,
                                             float* orow, int lane){
  float s=(v.x+v.y)+(v.z+v.w);
  #pragma unroll
  for(int o=16;o>0;o>>=1) s+=__shfl_xor_sync(0xffffffffu,s,o);
  float m=s*(1.f/128.f);
  float cx=v.x-m, cy=v.y-m, cz=v.z-m, cw=v.w-m;
  float q=(cx*cx+cy*cy)+(cz*cz+cw*cw);
  #pragma unroll
  for(int o=16;o>0;o>>=1) q+=__shfl_xor_sync(0xffffffffu,q,o);
  float inv=rsqrtf(q*(1.f/128.f)+gpf::EPS);
  float4 gv=*(const float4*)(g+lane*4), bv=*(const float4*)(bb+lane*4);
  float4 ov={cx*inv*gv.x+bv.x, cy*inv*gv.y+bv.y, cz*inv*gv.z+bv.z, cw*inv*gv.w+bv.w};
  *(float4*)(orow+lane*4)=ov;
}

// 3-pass bf16 GEMM: c[128d x 64p per warp] += A(h,[n][d]) ^T @ B(q,[n][p]); K=64
__device__ __forceinline__ void mma_gemm3(float c[8][4], uint32_t AH, uint32_t AL,
                                          uint32_t BH, uint32_t BL, int lane, int d0w, int pB){
  using namespace gpf;
  const int r=lane&7, g=lane>>3;
  const uint32_t aoff=(uint32_t)(((g&2)*4+r)*HB + (d0w+(g&1)*8)*2);
  const uint32_t brow=(uint32_t)(((g&1)*8+r)*HB);
  const uint32_t bcol=(uint32_t)((g>>1)*8*2);
  #pragma unroll
  for(int kk=0;kk<4;++kk){
    const uint32_t kb=(uint32_t)(kk*16*HB);
    uint32_t ah[4], al[4];
    LDSM4T(ah, AH+kb+aoff); LDSM4T(al, AL+kb+aoff);
    #pragma unroll
    for(int blk=0;blk<4;++blk){
      const uint32_t cb=(uint32_t)((pB+blk*16)*2)+bcol;
      uint32_t bh[4], bl[4];
      LDSM4T(bh, BH+kb+brow+cb); LDSM4T(bl, BL+kb+brow+cb);
      MMAB(c[2*blk],   ah, bh[0],bh[1]); MMAB(c[2*blk],   ah, bl[0],bl[1]); MMAB(c[2*blk],   al, bh[0],bh[1]);
      MMAB(c[2*blk+1], ah, bh[2],bh[3]); MMAB(c[2*blk+1], ah, bl[2],bl[3]); MMAB(c[2*blk+1], al, bh[2],bh[3]);
    }
  }
}

__global__ __launch_bounds__(gpf::NT,1)
void gpf_kernel(const float* __restrict__ w0g, const float* __restrict__ w1g,
                const float* __restrict__ w2g, const float* __restrict__ b0g,
                const float* __restrict__ b1g, const float* __restrict__ b2g,
                const float* __restrict__ xg,  const float* __restrict__ pwg,
                const float* __restrict__ pbg, const float* __restrict__ lngg,
                const float* __restrict__ lnbg, float* __restrict__ outg){
  using namespace gpf;
  extern __shared__ char smc[];
  const int b=blockIdx.x, t=threadIdx.x, lane=t&31, wid=t>>5;
  float* w1s=(float*)(smc+BY_W1);
  char *h1h=smc+BY_H1H, *h1l=smc+BY_H1L, *h2h=smc+BY_H2H, *h2l=smc+BY_H2L;
  char *q1h=smc+BY_Q1H, *q1l=smc+BY_Q1L, *q2h=smc+BY_Q2H, *q2l=smc+BY_Q2L;
  float* w0s=(float*)(smc+BY_W0); float* b0s=(float*)(smc+BY_B0); float* b1s=(float*)(smc+BY_B1);
  float* w2s=(float*)(smc+BY_W2); float* b2s=(float*)(smc+BY_B2);
  float* h3s=(float*)(smc+BY_H3); float* z5s=(float*)(smc+BY_Z5);
  const uint32_t H1H=smem_u32(h1h), H1L=smem_u32(h1l), H2H=smem_u32(h2h), H2L=smem_u32(h2l);
  const uint32_t Q1H=smem_u32(q1h), Q1L=smem_u32(q1l), Q2H=smem_u32(q2h), Q2L=smem_u32(q2l);

  { // one-time loads
    const float4* src=(const float4*)(w1g+(size_t)b*Hh*Hh); float4* dst=(float4*)w1s;
    #pragma unroll
    for(int i=0;i<8;++i) dst[t+i*NT]=src[t+i*NT];
    if(t<256) w0s[t]=w0g[b*256+t];
    else if(t<384) b0s[t-256]=b0g[b*128+(t-256)];
    else b1s[t-384]=b1g[b*128+(t-384)];
    if(t<128){
      w2s[t*4+0]=w2g[b*384+t*3+0]; w2s[t*4+1]=w2g[b*384+t*3+1]; w2s[t*4+2]=w2g[b*384+t*3+2];
    }
    if(t<3) b2s[t]=b2g[b*3+t];
  }

  float c1[8][4], c2[8][4];
  #pragma unroll
  for(int i=0;i<8;++i){ c1[i][0]=c1[i][1]=c1[i][2]=c1[i][3]=0.f; c2[i][0]=c2[i][1]=c2[i][2]=c2[i][3]=0.f; }
  float z3acc=0.f, z0a0=0.f, z0a1=0.f;
  const int d0w=(wid&7)*16, pB=(wid>>3)*64;
  const int nA=t>>3, dp0=t&7;           // Phase A mapping
  const int p2=t&63, nq0=t>>6;          // pw convert mapping

  for(int tile=0; tile<NTILES; ++tile){
    const int n0=tile*TILE;
    __syncthreads();

    { // Phase A: h1 = sin(30*(x@w0+b0)) -> bf16 hi/lo [n][d]; convert pw1,pw2 -> bf16 hi/lo [n][p]
      float x0=xg[(n0+nA)*2+0], x1=xg[(n0+nA)*2+1];
      char* hp=h1h+nA*HB; char* lp=h1l+nA*HB;
      #pragma unroll
      for(int it=0; it<8; ++it){
        int dp=dp0+it*8, h=dp*2;
        float s0=__sinf(W0F*fmaf(x0,w0s[h],  fmaf(x1,w0s[128+h],  b0s[h])));
        float s1=__sinf(W0F*fmaf(x0,w0s[h+1],fmaf(x1,w0s[128+h+1],b0s[h+1])));
        uint32_t lo, hi=bfpair(s0,s1,lo);
        *(uint32_t*)(hp+dp*4)=hi; *(uint32_t*)(lp+dp*4)=lo;
      }
      #pragma unroll
      for(int it=0; it<8; ++it){
        int n2=nq0+it*8;
        float2 v1=*(const float2*)(pwg+(size_t)1*Nn*Pp+(size_t)(n0+n2)*Pp+2*p2);
        float2 v2=*(const float2*)(pwg+(size_t)2*Nn*Pp+(size_t)(n0+n2)*Pp+2*p2);
        uint32_t lo1, hi1=bfpair(v1.x,v1.y,lo1);
        uint32_t lo2, hi2=bfpair(v2.x,v2.y,lo2);
        *(uint32_t*)(q1h+n2*HB+p2*4)=hi1; *(uint32_t*)(q1l+n2*HB+p2*4)=lo1;
        *(uint32_t*)(q2h+n2*HB+p2*4)=hi2; *(uint32_t*)(q2l+n2*HB+p2*4)=lo2;
      }
    }
    __syncthreads();

    { // Phase B: h2 = sin(30*(h1@w1+b1)) on fp32 FFMA2; write h2 bf16 hi/lo
      const int nb=wid*4, ob=lane*4;
      unsigned long long acc[4][2];
      #pragma unroll
      for(int i=0;i<4;++i){ acc[i][0]=0ull; acc[i][1]=0ull; }
      #pragma unroll 2
      for(int k4=0;k4<Hh;k4+=4){
        float a[4][4];
        #pragma unroll
        for(int i=0;i<4;++i){
          uint2 hh=*(const uint2*)(h1h+(nb+i)*HB+k4*2);
          uint2 ll=*(const uint2*)(h1l+(nb+i)*HB+k4*2);
          float2 f0=b2f(hh.x), f1=b2f(hh.y), g0=b2f(ll.x), g1=b2f(ll.y);
          a[i][0]=f0.x+g0.x; a[i][1]=f0.y+g0.y; a[i][2]=f1.x+g1.x; a[i][3]=f1.y+g1.y;
        }
        #pragma unroll
        for(int kk=0;kk<4;++kk){
          ulonglong2 bp=*(const ulonglong2*)(w1s+(k4+kk)*Hh+ob);
          unsigned long long ad;
          ad=pk2(a[0][kk],a[0][kk]); fma2(acc[0][0],ad,bp.x); fma2(acc[0][1],ad,bp.y);
          ad=pk2(a[1][kk],a[1][kk]); fma2(acc[1][0],ad,bp.x); fma2(acc[1][1],ad,bp.y);
          ad=pk2(a[2][kk],a[2][kk]); fma2(acc[2][0],ad,bp.x); fma2(acc[2][1],ad,bp.y);
          ad=pk2(a[3][kk],a[3][kk]); fma2(acc[3][0],ad,bp.x); fma2(acc[3][1],ad,bp.y);
        }
      }
      float bb0=b1s[ob],bb1=b1s[ob+1],bb2=b1s[ob+2],bb3=b1s[ob+3];
      #pragma unroll
      for(int i=0;i<4;++i){
        float2 u=upk2(acc[i][0]), v=upk2(acc[i][1]);
        float h0=__sinf(W0F*(u.x+bb0)), h1v=__sinf(W0F*(u.y+bb1));
        float h2v=__sinf(W0F*(v.x+bb2)), h3v=__sinf(W0F*(v.y+bb3));
        uint32_t lo0, hi0=bfpair(h0,h1v,lo0);
        uint32_t lo1, hi1=bfpair(h2v,h3v,lo1);
        unsigned long long H=(unsigned long long)hi0|((unsigned long long)hi1<<32);
        unsigned long long L=(unsigned long long)lo0|((unsigned long long)lo1<<32);
        *(unsigned long long*)(h2h+(nb+i)*HB+ob*2)=H;
        *(unsigned long long*)(h2l+(nb+i)*HB+ob*2)=L;
      }
    }

    // Phase C: z1 += h1^T @ pw1 (bf16 3-pass HMMA; h1/q1 ready since sync1)
    mma_gemm3(c1, H1H,H1L, Q1H,Q1L, lane, d0w, pB);

    __syncthreads();

    // Phase E (warps 10-15): h3 from h2 bf16
    if(t>=320){
      int u=t-320, n=u/3, j=u-n*3;
      float acc=b2s[j];
      #pragma unroll 4
      for(int k2=0;k2<64;++k2){
        float2 f=b2f(*(const uint32_t*)(h2h+n*HB+k2*4));
        float2 g=b2f(*(const uint32_t*)(h2l+n*HB+k2*4));
        acc=fmaf(f.x+g.x, w2s[(2*k2)*4+j], acc);
        acc=fmaf(f.y+g.y, w2s[(2*k2+1)*4+j], acc);
      }
      h3s[n*4+j]=acc;
    }

    // Phase D: z2 += h2^T @ pw2
    mma_gemm3(c2, H2H,H2L, Q2H,Q2L, lane, d0w, pB);

    __syncthreads();

    if(t<384){ // z3 += h3^T @ pw3 (pw3 streamed from L2)
      int j=t>>7, p=t&127;
      const float* pw3=pwg+(size_t)3*Nn*Pp+(size_t)n0*Pp+p;
      float ta=0.f, tb=0.f;
      #pragma unroll 8
      for(int n=0;n<TILE;n+=2){
        ta=fmaf(h3s[n*4+j],     pw3[n*Pp],     ta);
        tb=fmaf(h3s[(n+1)*4+j], pw3[(n+1)*Pp], tb);
      }
      z3acc+=ta+tb;
    } else { // z0 partial on warps 12-15
      int p=t-384;
      const float* pw0=pwg+(size_t)n0*Pp+p;
      const float* xp=xg+n0*2;
      float a0=0.f, a1=0.f;
      #pragma unroll 8
      for(int n=0;n<TILE;++n){ float w=pw0[n*Pp]; a0=fmaf(xp[n*2],w,a0); a1=fmaf(xp[n*2+1],w,a1); }
      z0a0+=a0; z0a1+=a1;
    }
  }

  // ===== epilogue =====
  __syncthreads();
  float* zs=(float*)smc;  // w1 dead
  const int rb=d0w+(lane>>2), cb0=pB+2*(lane&3);
  { // stage z1 + pb1
    const float* pb1=pbg+128;
    #pragma unroll
    for(int bb=0;bb<8;++bb){
      int col=cb0+bb*8;
      zs[rb*128+col]      =c1[bb][0]+pb1[col];
      zs[rb*128+col+1]    =c1[bb][1]+pb1[col+1];
      zs[(rb+8)*128+col]  =c1[bb][2]+pb1[col];
      zs[(rb+8)*128+col+1]=c1[bb][3]+pb1[col+1];
    }
  }
  __syncthreads();
  {
    const float* g=lngg+128; const float* bb=lnbg+128;
    #pragma unroll
    for(int r=0;r<8;++r){
      int row=wid*8+r;
      float4 v=*(const float4*)(zs+row*128+lane*4);
      ln_row_write(v,g,bb,outg+((size_t)b*ROWS+2+row)*Pp,lane);
    }
  }
  __syncthreads();
  { // stage z2 + pb2
    const float* pb2=pbg+256;
    #pragma unroll
    for(int bb=0;bb<8;++bb){
      int col=cb0+bb*8;
      zs[rb*128+col]      =c2[bb][0]+pb2[col];
      zs[rb*128+col+1]    =c2[bb][1]+pb2[col+1];
      zs[(rb+8)*128+col]  =c2[bb][2]+pb2[col];
      zs[(rb+8)*128+col+1]=c2[bb][3]+pb2[col+1];
    }
  }
  __syncthreads();
  {
    const float* g=lngg+256; const float* bb=lnbg+256;
    #pragma unroll
    for(int r=0;r<8;++r){
      int row=wid*8+r;
      float4 v=*(const float4*)(zs+row*128+lane*4);
      ln_row_write(v,g,bb,outg+((size_t)b*ROWS+130+row)*Pp,lane);
    }
  }
  if(t>=384){
    int p=t-384;
    z5s[p]=z0a0+pbg[p]; z5s[Pp+p]=z0a1+pbg[p];
  }
  if(t<384){
    int j=t>>7, p=t&127;
    z5s[(2+j)*Pp+p]=z3acc+pbg[3*128+p];
  }
  __syncthreads();
  if(wid<5){
    int row=wid, feat=(row<2)?0:3, outrow=(row<2)?row:(256+row);
    float4 v=*(const float4*)(z5s+row*Pp+lane*4);
    ln_row_write(v, lngg+feat*128, lnbg+feat*128,
                 outg+((size_t)b*ROWS+outrow)*Pp, lane);
  }
}

extern "C" void kernel_launch(void* const* d_in, const int* in_sizes, int n_in,
                              void* d_out, int out_size){
  (void)in_sizes;(void)n_in;(void)out_size;
  cudaFuncSetAttribute(gpf_kernel, cudaFuncAttributeMaxDynamicSharedMemorySize, gpf::SMEM_BYTES);
  gpf_kernel<<<gpf::Bn, gpf::NT, gpf::SMEM_BYTES>>>(
    (const float*)d_in[0],(const float*)d_in[1],(const float*)d_in[2],(const float*)d_in[3],
    (const float*)d_in[4],(const float*)d_in[5],(const float*)d_in[6],(const float*)d_in[7],
    (const float*)d_in[8],(const float*)d_in[9],(const float*)d_in[10],(float*)d_out);
}

// round 10
// speedup vs baseline: 1.9654x; 1.7251x over previous
#include <cuda_runtime.h>
#include <cuda_bf16.h>
#include <cstdint>

namespace gpf {
constexpr int Bn=128, Nn=4096, Pp=128, ROWS=261, TILE=64, NTILES=64, NT=512;
constexpr float W0F=30.f, EPS=1e-5f;
constexpr int SQ=272;   // byte stride: w1 [k][o], q [n][p]
constexpr int SH=144;   // byte stride: h tiles [d][n]
constexpr int BY_W1H=0, BY_W1L=34816;                                   // 128x272 x2
constexpr int BY_H1H=69632, BY_H1L=BY_H1H+18432, BY_H2H=BY_H1L+18432, BY_H2L=BY_H2H+18432;
constexpr int BY_Q1H=143360, BY_Q1L=BY_Q1H+17408, BY_Q2H=BY_Q1L+17408, BY_Q2L=BY_Q2H+17408;
constexpr int BY_W0=212992, BY_B0=BY_W0+1024, BY_B1=BY_B0+512, BY_W2=BY_B1+512,
  BY_B2=BY_W2+2048, BY_H3=BY_B2+32, BY_Z5=BY_H3+1024;
constexpr int SMEM_BYTES=BY_Z5+2560;  // 220704
}

#define LDSM4T(d,a) asm volatile( \
  "ldmatrix.sync.aligned.m8n8.x4.trans.shared.b16 {%0,%1,%2,%3},[%4];" \
  :"=r"((d)[0]),"=r"((d)[1]),"=r"((d)[2]),"=r"((d)[3]):"r"(a))
#define LDSM4(d,a) asm volatile( \
  "ldmatrix.sync.aligned.m8n8.x4.shared.b16 {%0,%1,%2,%3},[%4];" \
  :"=r"((d)[0]),"=r"((d)[1]),"=r"((d)[2]),"=r"((d)[3]):"r"(a))
#define MMAB(c,a,b0,b1) asm volatile( \
  "mma.sync.aligned.m16n8k16.row.col.f32.bf16.bf16.f32 " \
  "{%0,%1,%2,%3},{%4,%5,%6,%7},{%8,%9},{%0,%1,%2,%3};" \
  :"+f"((c)[0]),"+f"((c)[1]),"+f"((c)[2]),"+f"((c)[3]) \
  :"r"((a)[0]),"r"((a)[1]),"r"((a)[2]),"r"((a)[3]),"r"(b0),"r"(b1))

__device__ __forceinline__ uint32_t smem_u32(const void* p){
  uint32_t a; asm("{ .reg .u64 t; cvta.to.shared.u64 t, %1; cvt.u32.u64 %0, t; }":"=r"(a):"l"(p)); return a;
}
__device__ __forceinline__ uint32_t bfpair(float a, float b, uint32_t& lo){
  __nv_bfloat16 ha=__float2bfloat16(a), hb=__float2bfloat16(b);
  __nv_bfloat162 l; l.x=__float2bfloat16(a-__bfloat162float(ha)); l.y=__float2bfloat16(b-__bfloat162float(hb));
  lo=*(uint32_t*)&l;
  __nv_bfloat162 h; h.x=ha; h.y=hb; return *(uint32_t*)&h;
}
__device__ __forceinline__ void ln_row_write(float4 v, const float* g, const float* bb,
                                             float* orow, int lane){
  float s=(v.x+v.y)+(v.z+v.w);
  #pragma unroll
  for(int o=16;o>0;o>>=1) s+=__shfl_xor_sync(0xffffffffu,s,o);
  float m=s*(1.f/128.f);
  float cx=v.x-m, cy=v.y-m, cz=v.z-m, cw=v.w-m;
  float q=(cx*cx+cy*cy)+(cz*cz+cw*cw);
  #pragma unroll
  for(int o=16;o>0;o>>=1) q+=__shfl_xor_sync(0xffffffffu,q,o);
  float inv=rsqrtf(q*(1.f/128.f)+gpf::EPS);
  float4 gv=*(const float4*)(g+lane*4), bv=*(const float4*)(bb+lane*4);
  float4 ov={cx*inv*gv.x+bv.x, cy*inv*gv.y+bv.y, cz*inv*gv.z+bv.z, cw*inv*gv.w+bv.w};
  *(float4*)(orow+lane*4)=ov;
}

// 3-pass bf16 MMA, A TRANS from [k][m] stride SA; B TRANS from [k][j] stride SB.
template<int KS, int NB8>
__device__ __forceinline__ void gemm3_t(float (*c)[4], uint32_t AH, uint32_t AL,
    uint32_t BH, uint32_t BL, int lane, int m0, int j0, int SA, int SB){
  const int r=lane&7, g=lane>>3;
  const uint32_t ao=(uint32_t)(((g&2)*4+r)*SA + (m0+(g&1)*8)*2);
  const uint32_t bo=(uint32_t)(((g&1)*8+r)*SB + (g>>1)*16 + j0*2);
  #pragma unroll
  for(int kk=0;kk<KS;++kk){
    uint32_t ah[4], al[4];
    LDSM4T(ah, AH+kk*16*SA+ao); LDSM4T(al, AL+kk*16*SA+ao);
    #pragma unroll
    for(int b2=0;b2<NB8/2;++b2){
      uint32_t bh[4], bl[4], cb=(uint32_t)(kk*16*SB)+bo+b2*32;
      LDSM4T(bh, BH+cb); LDSM4T(bl, BL+cb);
      MMAB(c[2*b2],ah,bh[0],bh[1]); MMAB(c[2*b2],ah,bl[0],bl[1]); MMAB(c[2*b2],al,bh[0],bh[1]);
      MMAB(c[2*b2+1],ah,bh[2],bh[3]); MMAB(c[2*b2+1],ah,bl[2],bl[3]); MMAB(c[2*b2+1],al,bh[2],bh[3]);
    }
  }
}
// 3-pass bf16 MMA, A NON-TRANS from [m][k] stride SA; B TRANS from [k][j] stride SB.
template<int KS, int NB8>
__device__ __forceinline__ void gemm3_nt(float (*c)[4], uint32_t AH, uint32_t AL,
    uint32_t BH, uint32_t BL, int lane, int m0, int j0, int SA, int SB){
  const int r=lane&7, g=lane>>3;
  const uint32_t ao=(uint32_t)((m0+(g&1)*8+r)*SA + (g&2)*8);
  const uint32_t bo=(uint32_t)(((g&1)*8+r)*SB + (g>>1)*16 + j0*2);
  #pragma unroll
  for(int kk=0;kk<KS;++kk){
    uint32_t ah[4], al[4];
    LDSM4(ah, AH+kk*32+ao); LDSM4(al, AL+kk*32+ao);
    #pragma unroll
    for(int b2=0;b2<NB8/2;++b2){
      uint32_t bh[4], bl[4], cb=(uint32_t)(kk*16*SB)+bo+b2*32;
      LDSM4T(bh, BH+cb); LDSM4T(bl, BL+cb);
      MMAB(c[2*b2],ah,bh[0],bh[1]); MMAB(c[2*b2],ah,bl[0],bl[1]); MMAB(c[2*b2],al,bh[0],bh[1]);
      MMAB(c[2*b2+1],ah,bh[2],bh[3]); MMAB(c[2*b2+1],ah,bl[2],bl[3]); MMAB(c[2*b2+1],al,bh[2],bh[3]);
    }
  }
}

__global__ __launch_bounds__(gpf::NT,1)
void gpf_kernel(const float* __restrict__ w0g, const float* __restrict__ w1g,
                const float* __restrict__ w2g, const float* __restrict__ b0g,
                const float* __restrict__ b1g, const float* __restrict__ b2g,
                const float* __restrict__ xg,  const float* __restrict__ pwg,
                const float* __restrict__ pbg, const float* __restrict__ lngg,
                const float* __restrict__ lnbg, float* __restrict__ outg){
  using namespace gpf;
  extern __shared__ char smc[];
  const int b=blockIdx.x, t=threadIdx.x, lane=t&31, wid=t>>5;
  char *w1h=smc+BY_W1H, *w1l=smc+BY_W1L;
  char *h1h=smc+BY_H1H, *h1l=smc+BY_H1L, *h2h=smc+BY_H2H, *h2l=smc+BY_H2L;
  char *q1h=smc+BY_Q1H, *q1l=smc+BY_Q1L, *q2h=smc+BY_Q2H, *q2l=smc+BY_Q2L;
  float* w0s=(float*)(smc+BY_W0); float* b0s=(float*)(smc+BY_B0); float* b1s=(float*)(smc+BY_B1);
  float* w2s=(float*)(smc+BY_W2); float* b2s=(float*)(smc+BY_B2);
  float* h3s=(float*)(smc+BY_H3); float* z5s=(float*)(smc+BY_Z5);
  const uint32_t W1H=smem_u32(w1h), W1L=smem_u32(w1l);
  const uint32_t H1H=smem_u32(h1h), H1L=smem_u32(h1l), H2H=smem_u32(h2h), H2L=smem_u32(h2l);
  const uint32_t Q1H=smem_u32(q1h), Q1L=smem_u32(q1l), Q2H=smem_u32(q2h), Q2L=smem_u32(q2l);

  { // one-time: w1 -> bf16 hi/lo [k][o]; params
    int po=t&63, k0=t>>6;
    #pragma unroll
    for(int it=0;it<16;++it){
      int k=k0+it*8;
      float2 v=*(const float2*)(w1g+(size_t)b*16384+k*128+2*po);
      uint32_t lo, hi=bfpair(v.x,v.y,lo);
      *(uint32_t*)(w1h+k*SQ+po*4)=hi; *(uint32_t*)(w1l+k*SQ+po*4)=lo;
    }
    if(t<256) w0s[t]=w0g[b*256+t];
    else if(t<384) b0s[t-256]=b0g[b*128+(t-256)];
    else b1s[t-384]=b1g[b*128+(t-384)];
    if(t<128){
      w2s[t*4+0]=w2g[b*384+t*3+0]; w2s[t*4+1]=w2g[b*384+t*3+1]; w2s[t*4+2]=w2g[b*384+t*3+2];
    }
    if(t<3) b2s[t]=b2g[b*3+t];
  }

  float c1[8][4], c2[8][4];
  #pragma unroll
  for(int i=0;i<8;++i){ c1[i][0]=c1[i][1]=c1[i][2]=c1[i][3]=0.f; c2[i][0]=c2[i][1]=c2[i][2]=c2[i][3]=0.f; }
  float z3acc=0.f, z0a0=0.f, z0a1=0.f;
  const int d0w=(wid&7)*16, pB=(wid>>3)*64;   // C/D: m-block (d), p-chunk
  const int oB=(wid&7)*16, nC=(wid>>3)*32;    // B: o-block, n-chunk
  const int p2=t&63, nq0=t>>6;

  for(int tile=0; tile<NTILES; ++tile){
    const int n0=tile*TILE;
    __syncthreads();

    { // Phase A: h1=sin(30*(x@w0+b0)) -> [d][n] bf16 hi/lo; convert pw1,pw2 -> [n][p]
      float4 xv=*(const float4*)(xg+(size_t)n0*2+lane*4);
      #pragma unroll
      for(int it=0;it<8;++it){
        int d=wid+it*16;
        float wa=w0s[d], wb=w0s[128+d], bi=b0s[d];
        float s0=__sinf(W0F*fmaf(xv.x,wa,fmaf(xv.y,wb,bi)));
        float s1=__sinf(W0F*fmaf(xv.z,wa,fmaf(xv.w,wb,bi)));
        uint32_t lo, hi=bfpair(s0,s1,lo);
        *(uint32_t*)(h1h+d*SH+lane*4)=hi; *(uint32_t*)(h1l+d*SH+lane*4)=lo;
      }
      #pragma unroll
      for(int it=0;it<8;++it){
        int n2=nq0+it*8;
        float2 v1=*(const float2*)(pwg+(size_t)1*Nn*Pp+(size_t)(n0+n2)*Pp+2*p2);
        float2 v2=*(const float2*)(pwg+(size_t)2*Nn*Pp+(size_t)(n0+n2)*Pp+2*p2);
        uint32_t lo1, hi1=bfpair(v1.x,v1.y,lo1);
        uint32_t lo2, hi2=bfpair(v2.x,v2.y,lo2);
        *(uint32_t*)(q1h+n2*SQ+p2*4)=hi1; *(uint32_t*)(q1l+n2*SQ+p2*4)=lo1;
        *(uint32_t*)(q2h+n2*SQ+p2*4)=hi2; *(uint32_t*)(q2l+n2*SQ+p2*4)=lo2;
      }
    }
    __syncthreads();

    { // Phase B (HMMA): h2^T[o][n] = sin(30*(w1^T-contract-d h1 + b1))
      float c[4][4];
      #pragma unroll
      for(int i=0;i<4;++i){ c[i][0]=c[i][1]=c[i][2]=c[i][3]=0.f; }
      gemm3_t<8,4>(c, W1H,W1L, H1H,H1L, lane, oB, nC, SQ, SH);
      int o0=oB+(lane>>2);
      float bia0=b1s[o0], bia1=b1s[o0+8];
      #pragma unroll
      for(int bb=0;bb<4;++bb){
        int n=nC+(bb>>1)*16+(bb&1)*8+2*(lane&3);
        float s0=__sinf(W0F*(c[bb][0]+bia0)), s1=__sinf(W0F*(c[bb][1]+bia0));
        float s2=__sinf(W0F*(c[bb][2]+bia1)), s3=__sinf(W0F*(c[bb][3]+bia1));
        uint32_t lo0, hi0=bfpair(s0,s1,lo0);
        uint32_t lo1, hi1=bfpair(s2,s3,lo1);
        *(uint32_t*)(h2h+o0*SH+n*2)=hi0;     *(uint32_t*)(h2l+o0*SH+n*2)=lo0;
        *(uint32_t*)(h2h+(o0+8)*SH+n*2)=hi1; *(uint32_t*)(h2l+(o0+8)*SH+n*2)=lo1;
      }
    }
    // Phase C: z1 += h1^T @ pw1  (A non-trans from [d][n])
    gemm3_nt<4,8>(c1, H1H,H1L, Q1H,Q1L, lane, d0w, pB, SH, SQ);
    __syncthreads();

    // Phase E (warps 10-15): h3[n][j] from h2^T
    if(t>=320){
      int u=t-320, n=u/3, j=u-n*3;
      float acc=b2s[j];
      #pragma unroll 8
      for(int o=0;o<128;++o){
        float hv=__bfloat162float(*(__nv_bfloat16*)(h2h+o*SH+n*2));
        float lv=__bfloat162float(*(__nv_bfloat16*)(h2l+o*SH+n*2));
        acc=fmaf(hv+lv, w2s[o*4+j], acc);
      }
      h3s[n*4+j]=acc;
    }
    // Phase D: z2 += h2^T-contract-n @ pw2
    gemm3_nt<4,8>(c2, H2H,H2L, Q2H,Q2L, lane, d0w, pB, SH, SQ);
    __syncthreads();

    if(t<384){ // z3 += h3^T @ pw3
      int j=t>>7, p=t&127;
      const float* pw3=pwg+(size_t)3*Nn*Pp+(size_t)n0*Pp+p;
      float ta=0.f, tb=0.f;
      #pragma unroll 8
      for(int n=0;n<TILE;n+=2){
        ta=fmaf(h3s[n*4+j],     pw3[n*Pp],     ta);
        tb=fmaf(h3s[(n+1)*4+j], pw3[(n+1)*Pp], tb);
      }
      z3acc+=ta+tb;
    } else { // z0 partial
      int p=t-384;
      const float* pw0=pwg+(size_t)n0*Pp+p;
      const float* xp=xg+n0*2;
      float a0=0.f, a1=0.f;
      #pragma unroll 8
      for(int n=0;n<TILE;++n){ float w=pw0[n*Pp]; a0=fmaf(xp[n*2],w,a0); a1=fmaf(xp[n*2+1],w,a1); }
      z0a0+=a0; z0a1+=a1;
    }
  }

  // ===== epilogue =====
  __syncthreads();
  float* zs=(float*)(smc+BY_H1H);  // h tiles dead: 64KB staging
  const int rb=d0w+(lane>>2), cb0=pB+2*(lane&3);
  {
    const float* pb1=pbg+128;
    #pragma unroll
    for(int bb=0;bb<8;++bb){
      int col=cb0+bb*8;
      zs[rb*128+col]      =c1[bb][0]+pb1[col];
      zs[rb*128+col+1]    =c1[bb][1]+pb1[col+1];
      zs[(rb+8)*128+col]  =c1[bb][2]+pb1[col];
      zs[(rb+8)*128+col+1]=c1[bb][3]+pb1[col+1];
    }
  }
  __syncthreads();
  {
    const float* g=lngg+128; const float* bb=lnbg+128;
    #pragma unroll
    for(int r=0;r<8;++r){
      int row=wid*8+r;
      float4 v=*(const float4*)(zs+row*128+lane*4);
      ln_row_write(v,g,bb,outg+((size_t)b*ROWS+2+row)*Pp,lane);
    }
  }
  __syncthreads();
  {
    const float* pb2=pbg+256;
    #pragma unroll
    for(int bb=0;bb<8;++bb){
      int col=cb0+bb*8;
      zs[rb*128+col]      =c2[bb][0]+pb2[col];
      zs[rb*128+col+1]    =c2[bb][1]+pb2[col+1];
      zs[(rb+8)*128+col]  =c2[bb][2]+pb2[col];
      zs[(rb+8)*128+col+1]=c2[bb][3]+pb2[col+1];
    }
  }
  __syncthreads();
  {
    const float* g=lngg+256; const float* bb=lnbg+256;
    #pragma unroll
    for(int r=0;r<8;++r){
      int row=wid*8+r;
      float4 v=*(const float4*)(zs+row*128+lane*4);
      ln_row_write(v,g,bb,outg+((size_t)b*ROWS+130+row)*Pp,lane);
    }
  }
  if(t>=384){
    int p=t-384;
    z5s[p]=z0a0+pbg[p]; z5s[Pp+p]=z0a1+pbg[p];
  }
  if(t<384){
    int j=t>>7, p=t&127;
    z5s[(2+j)*Pp+p]=z3acc+pbg[3*128+p];
  }
  __syncthreads();
  if(wid<5){
    int row=wid, feat=(row<2)?0:3, outrow=(row<2)?row:(256+row);
    float4 v=*(const float4*)(z5s+row*Pp+lane*4);
    ln_row_write(v, lngg+feat*128, lnbg+feat*128,
                 outg+((size_t)b*ROWS+outrow)*Pp, lane);
  }
}

extern "C" void kernel_launch(void* const* d_in, const int* in_sizes, int n_in,
                              void* d_out, int out_size){
  (void)in_sizes;(void)n_in;(void)out_size;
  cudaFuncSetAttribute(gpf_kernel, cudaFuncAttributeMaxDynamicSharedMemorySize, gpf::SMEM_BYTES);
  gpf_kernel<<<gpf::Bn, gpf::NT, gpf::SMEM_BYTES>>>(
    (const float*)d_in[0],(const float*)d_in[1],(const float*)d_in[2],(const float*)d_in[3],
    (const float*)d_in[4],(const float*)d_in[5],(const float*)d_in[6],(const float*)d_in[7],
    (const float*)d_in[8],(const float*)d_in[9],(const float*)d_in[10],(float*)d_out);
}